// round 17
// baseline (speedup 1.0000x reference)
#include <cuda_runtime.h>
#include <cuda_fp16.h>
#include <cstdint>

// Problem constants
#define Bn 8
#define Qn 900
#define EMBED 256
#define HEADS 8
#define LEVELS 4
#define POINTS 4
#define HEAD_DIM 32
#define NUM_KEYS 13294
#define BQ (Bn*Qn)            // 7200
#define MV (Bn*NUM_KEYS)      // 106352

#define NVB_Y ((MV + 127) / 128)      // 831 value row-tiles (BM=128)
#define NVB   (NVB_Y * 2)             // 1662 value CTAs
#define NQB_Y ((BQ + 63) / 64)        // 113 query row-tiles (BM=64)
#define NQB   (NQB_Y * 3)             // 339 qproj CTAs

// Transposed fp16 weight regions within g_wt (units: halfs)
#define WT_VAL  0
#define WT_OFF  65536
#define WT_ATTN 131072
#define WT_OUT  163840

// Scratch (device globals; no runtime allocation)
__device__ __half g_vh  [(size_t)MV * EMBED];  // projected value, fp16
__device__ float  g_qp  [(size_t)BQ * 384];    // [off(256) | attn(128)] per query
__device__ __half g_tmph[(size_t)BQ * 256];    // msda output, fp16
__device__ __half g_wt  [229376];              // all weights, [n][k] fp16

__device__ __forceinline__ uint32_t packh2(float a, float b) {
    __half2 h = __floats2half2_rn(a, b);
    return *reinterpret_cast<uint32_t*>(&h);
}
__device__ __forceinline__ uint32_t smem_u32(const void* p) {
    uint32_t a;
    asm("{ .reg .u64 t; cvta.to.shared.u64 t, %1; cvt.u32.u64 %0, t; }"
        : "=r"(a) : "l"(p));
    return a;
}
__device__ __forceinline__ void ldsm_x4(uint32_t& r0, uint32_t& r1,
                                        uint32_t& r2, uint32_t& r3, uint32_t addr) {
    asm volatile("ldmatrix.sync.aligned.m8n8.x4.shared.b16 {%0,%1,%2,%3}, [%4];"
                 : "=r"(r0), "=r"(r1), "=r"(r2), "=r"(r3) : "r"(addr));
}
__device__ __forceinline__ void cp_async16(uint32_t dst, const void* src) {
    asm volatile("cp.async.cg.shared.global [%0], [%1], 16;"
                 :: "r"(dst), "l"(src) : "memory");
}
#define CP_COMMIT() asm volatile("cp.async.commit_group;" ::: "memory")
#define CP_WAIT0()  asm volatile("cp.async.wait_group 0;" ::: "memory")
#define CP_WAIT1()  asm volatile("cp.async.wait_group 1;" ::: "memory")

#define HMMA16816(acc, a, b) \
    asm volatile( \
        "mma.sync.aligned.m16n8k16.row.col.f32.f16.f16.f32 " \
        "{%0,%1,%2,%3}, {%4,%5,%6,%7}, {%8,%9}, {%0,%1,%2,%3};" \
        : "+f"((acc)[0]), "+f"((acc)[1]), "+f"((acc)[2]), "+f"((acc)[3]) \
        : "r"((a)[0]), "r"((a)[1]), "r"((a)[2]), "r"((a)[3]), \
          "r"((b)[0]), "r"((b)[1]))

// ---------------------------------------------------------------------------
// Weight transpose+convert: W[k][n] f32 -> Wt[n][k] f16 (rounding == packh2).
// ---------------------------------------------------------------------------
__global__ void transpose_w(const float* __restrict__ W_val,
                            const float* __restrict__ W_off,
                            const float* __restrict__ W_attn,
                            const float* __restrict__ W_out,
                            __half* __restrict__ Wt)
{
    const float* W; int N; int base;
    switch (blockIdx.z) {
        case 0:  W = W_val;  N = 256; base = WT_VAL;  break;
        case 1:  W = W_off;  N = 256; base = WT_OFF;  break;
        case 2:  W = W_attn; N = 128; base = WT_ATTN; break;
        default: W = W_out;  N = 256; base = WT_OUT;  break;
    }
    const int n0 = blockIdx.x * 32, k0 = blockIdx.y * 32;
    if (n0 >= N) return;

    __shared__ float t[32][33];
    const int tx = threadIdx.x, ty = threadIdx.y;
    #pragma unroll
    for (int i = 0; i < 4; i++)
        t[tx][ty + 8 * i] = W[(size_t)(k0 + ty + 8 * i) * N + n0 + tx];
    __syncthreads();
    const int id = ty * 32 + tx;
    #pragma unroll
    for (int i = 0; i < 2; i++) {
        int e = id + i * 256, n = e >> 4, kk = e & 15;
        uint32_t h = packh2(t[n][2 * kk], t[n][2 * kk + 1]);
        *reinterpret_cast<uint32_t*>(Wt + base + (size_t)(n0 + n) * 256 + k0 + 2 * kk) = h;
    }
}

// ---------------------------------------------------------------------------
// GEMM core (round-16 validated): 256 threads, warp grid 2x4,
// warp tile (MI*16)x32, K=256 in 8 BK=32 stages. A double-buffered via regs,
// B triple-buffered via cp.async + wait_group 1.
// ---------------------------------------------------------------------------
template <int MI, bool HOUT>
__device__ __forceinline__ void gemm_tile(
    const float* __restrict__ A, int M, int brow,
    const __half* __restrict__ Bt,
    const float* __restrict__ biasb,
    void* __restrict__ Cb,
    int ldc,
    uint32_t* sm)
{
    constexpr int BM    = MI * 32;
    constexpr int AST   = 20;
    constexpr int ASZW  = BM * AST;
    constexpr int ASZB  = ASZW * 4;
    constexpr int BSZW  = 128 * AST;
    constexpr int BSZB  = BSZW * 4;

    const int tid  = threadIdx.x;
    const int lane = tid & 31;
    const int w    = tid >> 5;
    const int gid  = lane >> 2;
    const int tig  = lane & 3;
    const int m0   = (w >> 2) * (MI * 16);
    const int n0   = (w & 3) * 32;

    const uint32_t smbase = smem_u32(sm);
    const uint32_t aAddr = smbase + (uint32_t)(m0 + (lane & 15)) * 80
                                  + ((lane & 16) ? 16u : 0u);
    const uint32_t bAddr = smbase + (uint32_t)(2 * ASZB)
                                  + (uint32_t)(n0 + (lane & 7) + ((lane & 16) ? 8 : 0)) * 80
                                  + ((lane & 8) ? 16u : 0u);

    float acc[MI][4][4];
    #pragma unroll
    for (int mi = 0; mi < MI; mi++)
        #pragma unroll
        for (int nj = 0; nj < 4; nj++)
            #pragma unroll
            for (int r = 0; r < 4; r++) acc[mi][nj][r] = 0.f;

    float4 pa[MI];

    auto issueB = [&](int t) {
        const int k0 = t * 32;
        const int buf = t % 3;
        #pragma unroll
        for (int i = 0; i < 2; ++i) {
            int g = tid + i * 256, n = g >> 2, ch = g & 3;
            uint32_t dst = smbase + 2 * ASZB + (uint32_t)buf * BSZB
                         + (uint32_t)n * 80 + ch * 16;
            cp_async16(dst, Bt + (size_t)n * 256 + k0 + ch * 8);
        }
        CP_COMMIT();
    };
    auto loadA = [&](int k0) {
        #pragma unroll
        for (int i = 0; i < MI; ++i) {
            int c = tid + i * 256, row = c >> 3, slot = c & 7;
            int gr = min(brow + row, M - 1);
            pa[i] = *reinterpret_cast<const float4*>(A + (size_t)gr * 256 + k0 + slot * 4);
        }
    };
    auto storeA = [&](int p) {
        uint32_t* As = sm + p * ASZW;
        #pragma unroll
        for (int i = 0; i < MI; ++i) {
            int c = tid + i * 256, row = c >> 3, slot = c & 7;
            uint2 t = { packh2(pa[i].x, pa[i].y), packh2(pa[i].z, pa[i].w) };
            *reinterpret_cast<uint2*>(&As[row * AST + 2 * slot]) = t;
        }
    };
    auto compute = [&](int t) {
        const uint32_t pa_off = (uint32_t)(t & 1) * ASZB;
        const uint32_t pb_off = (uint32_t)(t % 3) * BSZB;
        #pragma unroll
        for (int ks = 0; ks < 2; ks++) {
            uint32_t a[MI][4], b[4][2];
            #pragma unroll
            for (int mi = 0; mi < MI; mi++)
                ldsm_x4(a[mi][0], a[mi][1], a[mi][2], a[mi][3],
                        aAddr + pa_off + mi * 1280 + ks * 32);
            #pragma unroll
            for (int njp = 0; njp < 2; njp++)
                ldsm_x4(b[2 * njp][0], b[2 * njp][1], b[2 * njp + 1][0], b[2 * njp + 1][1],
                        bAddr + pb_off + njp * 1280 + ks * 32);
            #pragma unroll
            for (int mi = 0; mi < MI; mi++)
                #pragma unroll
                for (int nj = 0; nj < 4; nj++)
                    HMMA16816(acc[mi][nj], a[mi], b[nj]);
        }
    };

    issueB(0);
    issueB(1);
    loadA(0);
    storeA(0);
    CP_WAIT1();
    __syncthreads();
    #pragma unroll 1
    for (int t = 0; t < 8; t++) {
        if (t < 6) issueB(t + 2);
        if (t < 7) loadA((t + 1) * 32);
        compute(t);
        if (t < 7) storeA((t + 1) & 1);
        if (t < 6) CP_WAIT1();
        else if (t == 6) CP_WAIT0();
        __syncthreads();
    }

    // Epilogue
    #pragma unroll
    for (int mi = 0; mi < MI; mi++) {
        #pragma unroll
        for (int nj = 0; nj < 4; nj++) {
            int col = n0 + nj * 8 + 2 * tig;
            float b0 = biasb[col], b1 = biasb[col + 1];
            int r0 = brow + m0 + mi * 16 + gid;
            int r1 = r0 + 8;
            if (HOUT) {
                __half* C = (__half*)Cb;
                if (r0 < M)
                    *reinterpret_cast<uint32_t*>(C + (size_t)r0 * ldc + col) =
                        packh2(acc[mi][nj][0] + b0, acc[mi][nj][1] + b1);
                if (r1 < M)
                    *reinterpret_cast<uint32_t*>(C + (size_t)r1 * ldc + col) =
                        packh2(acc[mi][nj][2] + b0, acc[mi][nj][3] + b1);
            } else {
                float* C = (float*)Cb;
                if (r0 < M) {
                    float2 v0 = make_float2(acc[mi][nj][0] + b0, acc[mi][nj][1] + b1);
                    *reinterpret_cast<float2*>(C + (size_t)r0 * ldc + col) = v0;
                }
                if (r1 < M) {
                    float2 v1 = make_float2(acc[mi][nj][2] + b0, acc[mi][nj][3] + b1);
                    *reinterpret_cast<float2*>(C + (size_t)r1 * ldc + col) = v1;
                }
            }
        }
    }
}

// ---------------------------------------------------------------------------
// Fused mega-launch: value (1662 CTAs, BM=128) + qproj (339 CTAs, BM=64).
// ---------------------------------------------------------------------------
__global__ __launch_bounds__(256, 2) void gemm_fused(
    const float* __restrict__ value, const float* __restrict__ query,
    const __half* __restrict__ wt,
    const float* __restrict__ b_val, const float* __restrict__ b_off,
    const float* __restrict__ b_attn,
    __half* __restrict__ vh, float* __restrict__ qp)
{
    extern __shared__ uint32_t sm[];
    const int bid = blockIdx.x;

    if (bid < NVB) {
        const int ty = bid >> 1, tx = bid & 1;
        gemm_tile<4, true>(value, MV, ty * 128,
                           wt + WT_VAL + (size_t)tx * 128 * 256, b_val + tx * 128,
                           vh + tx * 128, 256, sm);
    } else {
        const int q = bid - NVB;
        const int ty = q / 3, tx = q % 3;
        const __half* Bp = (tx < 2) ? (wt + WT_OFF + (size_t)tx * 128 * 256)
                                    : (wt + WT_ATTN);
        const float*  bb = (tx < 2) ? (b_off + tx * 128) : b_attn;
        gemm_tile<2, false>(query, BQ, ty * 64,
                            Bp, bb,
                            qp + tx * 128, 384, sm);
    }
}

// ---------------------------------------------------------------------------
// Output projection: single-stage full-K, BM=32 x BN=128 (450 CTAs).
// Smem rows hold K=256 halfs (512B data, 528B stride; bank walk 4r
// conflict-free). One cp.async burst, one wait+sync, 16 HMMA k-steps.
// ---------------------------------------------------------------------------
__global__ __launch_bounds__(256, 2) void gemm_out(
    const __half* __restrict__ A,      // tmp fp16 [BQ][256]
    const __half* __restrict__ wt, const float* __restrict__ bias,
    float* __restrict__ C)
{
    constexpr int RSTB = 528;              // bytes per smem row
    constexpr int ASZB = 32 * RSTB;        // 16896 B

    extern __shared__ uint32_t sm[];
    const int tid  = threadIdx.x;
    const int lane = tid & 31;
    const int w    = tid >> 5;
    const int gid  = lane >> 2;
    const int tig  = lane & 3;
    const int brow = blockIdx.y * 32;
    const int txb  = blockIdx.x;
    const __half* Bt = wt + WT_OUT + (size_t)txb * 128 * 256;
    const int m0 = (w >> 2) * 16;          // MI=1: 2 warp rows of 16
    const int n0 = (w & 3) * 32;

    const uint32_t smbase = smem_u32(sm);

    // A: 32 rows x 32 16B-chunks = 1024 cp.async -> 4/thread
    #pragma unroll
    for (int i = 0; i < 4; i++) {
        int g = tid + i * 256, row = g >> 5, ch = g & 31;
        int gr = min(brow + row, BQ - 1);
        cp_async16(smbase + (uint32_t)row * RSTB + ch * 16,
                   A + (size_t)gr * 256 + ch * 8);
    }
    // B: 128 rows x 32 chunks = 4096 -> 16/thread
    #pragma unroll
    for (int i = 0; i < 16; i++) {
        int g = tid + i * 256, n = g >> 5, ch = g & 31;
        cp_async16(smbase + ASZB + (uint32_t)n * RSTB + ch * 16,
                   Bt + (size_t)n * 256 + ch * 8);
    }
    CP_COMMIT();
    CP_WAIT0();
    __syncthreads();

    const uint32_t aAddr = smbase + (uint32_t)(m0 + (lane & 15)) * RSTB
                                  + ((lane & 16) ? 16u : 0u);
    const uint32_t bAddr = smbase + ASZB
                                  + (uint32_t)(n0 + (lane & 7) + ((lane & 16) ? 8 : 0)) * RSTB
                                  + ((lane & 8) ? 16u : 0u);

    float acc[4][4];
    #pragma unroll
    for (int nj = 0; nj < 4; nj++)
        #pragma unroll
        for (int r = 0; r < 4; r++) acc[nj][r] = 0.f;

    #pragma unroll
    for (int kk = 0; kk < 16; kk++) {
        uint32_t a[4], b[4][2];
        ldsm_x4(a[0], a[1], a[2], a[3], aAddr + kk * 32);
        #pragma unroll
        for (int njp = 0; njp < 2; njp++)
            ldsm_x4(b[2 * njp][0], b[2 * njp][1], b[2 * njp + 1][0], b[2 * njp + 1][1],
                    bAddr + njp * 16 * RSTB + kk * 32);
        #pragma unroll
        for (int nj = 0; nj < 4; nj++)
            HMMA16816(acc[nj], a, b[nj]);
    }

    #pragma unroll
    for (int nj = 0; nj < 4; nj++) {
        int col = txb * 128 + n0 + nj * 8 + 2 * tig;
        float b0 = bias[col], b1 = bias[col + 1];
        int r0 = brow + m0 + gid;
        int r1 = r0 + 8;
        if (r0 < BQ) {
            float2 v0 = make_float2(acc[nj][0] + b0, acc[nj][1] + b1);
            *reinterpret_cast<float2*>(C + (size_t)r0 * 256 + col) = v0;
        }
        if (r1 < BQ) {
            float2 v1 = make_float2(acc[nj][2] + b0, acc[nj][3] + b1);
            *reinterpret_cast<float2*>(C + (size_t)r1 * 256 + col) = v1;
        }
    }
}

// ---------------------------------------------------------------------------
// Fused softmax + sampling over fp16 value; writes tmp as fp16.
// Lane = 4*sg4 + ... : sg4 = lane>>2 (8 sample pairs), c4 = lane&3 owns 8
// channels via one LDG.128 per corner. xor-4/8/16 reduction, uint4 store.
// ---------------------------------------------------------------------------
__global__ __launch_bounds__(256) void msda_sample(
    const float* __restrict__ ref, const float* __restrict__ qp,
    const int* __restrict__ shapes, const int* __restrict__ starts,
    const __half* __restrict__ v, __half* __restrict__ tmp)
{
    const int bq  = blockIdx.x;
    const int b   = bq / Qn;
    const int tid = threadIdx.x;

    __shared__ int4   sIdx[128];
    __shared__ float4 sW[128];

    if (tid < 128) {
        const int l = (tid >> 2) & 3;
        const int Hl = shapes[2 * l], Wl = shapes[2 * l + 1];
        const int st = starts[l];

        float logit = qp[(size_t)bq * 384 + 256 + tid];
        float m = logit;
        #pragma unroll
        for (int d = 8; d >= 1; d >>= 1)
            m = fmaxf(m, __shfl_xor_sync(0xffffffffu, m, d));
        float e = __expf(logit - m);
        float s = e;
        #pragma unroll
        for (int d = 8; d >= 1; d >>= 1)
            s += __shfl_xor_sync(0xffffffffu, s, d);
        const float wgt = e / s;

        const float2 off = reinterpret_cast<const float2*>(qp + (size_t)bq * 384)[tid];
        const float rx = ref[(size_t)bq * (LEVELS * 2) + 2 * l];
        const float ry = ref[(size_t)bq * (LEVELS * 2) + 2 * l + 1];
        const float x = rx * (float)Wl + off.x - 0.5f;
        const float y = ry * (float)Hl + off.y - 0.5f;

        const float x0f = floorf(x), y0f = floorf(y);
        const int x0 = (int)x0f, y0 = (int)y0f;
        const float fx = x - x0f, fy = y - y0f;
        const int x1 = x0 + 1, y1 = y0 + 1;
        const bool bx0 = (x0 >= 0) & (x0 < Wl);
        const bool bx1 = (x1 >= 0) & (x1 < Wl);
        const bool by0 = (y0 >= 0) & (y0 < Hl);
        const bool by1 = (y1 >= 0) & (y1 < Hl);
        const int cx0 = min(max(x0, 0), Wl - 1), cx1 = min(max(x1, 0), Wl - 1);
        const int cy0 = min(max(y0, 0), Hl - 1), cy1 = min(max(y1, 0), Hl - 1);

        sIdx[tid] = make_int4(st + cy0 * Wl + cx0, st + cy0 * Wl + cx1,
                              st + cy1 * Wl + cx0, st + cy1 * Wl + cx1);
        sW[tid] = make_float4(
            (bx0 && by0) ? (1.f - fx) * (1.f - fy) * wgt : 0.f,
            (bx1 && by0) ? fx * (1.f - fy) * wgt : 0.f,
            (bx0 && by1) ? (1.f - fx) * fy * wgt : 0.f,
            (bx1 && by1) ? fx * fy * wgt : 0.f);
    }
    __syncthreads();

    const int h    = tid >> 5;
    const int lane = tid & 31;
    const int sg4  = lane >> 2;          // 8 sample pairs
    const int c4   = lane & 3;           // 8-channel group
    const __half* vb = v + (size_t)b * NUM_KEYS * EMBED + h * HEAD_DIM + 8 * c4;

    float a0 = 0.f, a1 = 0.f, a2 = 0.f, a3 = 0.f;
    float a4 = 0.f, a5 = 0.f, a6 = 0.f, a7 = 0.f;
    #pragma unroll
    for (int j = 0; j < 2; j++) {
        const int s = h * 16 + sg4 * 2 + j;
        const int4   id = sIdx[s];
        const float4 wv = sW[s];
        uint4 r0 = *reinterpret_cast<const uint4*>(vb + (size_t)id.x * EMBED);
        uint4 r1 = *reinterpret_cast<const uint4*>(vb + (size_t)id.y * EMBED);
        uint4 r2 = *reinterpret_cast<const uint4*>(vb + (size_t)id.z * EMBED);
        uint4 r3 = *reinterpret_cast<const uint4*>(vb + (size_t)id.w * EMBED);
        #pragma unroll
        for (int c = 0; c < 4; c++) {
            uint32_t u0 = (&r0.x)[c], u1 = (&r1.x)[c], u2 = (&r2.x)[c], u3 = (&r3.x)[c];
            float2 g0 = __half22float2(*reinterpret_cast<__half2*>(&u0));
            float2 g1 = __half22float2(*reinterpret_cast<__half2*>(&u1));
            float2 g2 = __half22float2(*reinterpret_cast<__half2*>(&u2));
            float2 g3 = __half22float2(*reinterpret_cast<__half2*>(&u3));
            float sx = wv.x * g0.x + wv.y * g1.x + wv.z * g2.x + wv.w * g3.x;
            float sy = wv.x * g0.y + wv.y * g1.y + wv.z * g2.y + wv.w * g3.y;
            switch (c) {
                case 0: a0 += sx; a1 += sy; break;
                case 1: a2 += sx; a3 += sy; break;
                case 2: a4 += sx; a5 += sy; break;
                case 3: a6 += sx; a7 += sy; break;
            }
        }
    }
    #pragma unroll
    for (int d = 4; d <= 16; d <<= 1) {
        a0 += __shfl_xor_sync(0xffffffffu, a0, d);
        a1 += __shfl_xor_sync(0xffffffffu, a1, d);
        a2 += __shfl_xor_sync(0xffffffffu, a2, d);
        a3 += __shfl_xor_sync(0xffffffffu, a3, d);
        a4 += __shfl_xor_sync(0xffffffffu, a4, d);
        a5 += __shfl_xor_sync(0xffffffffu, a5, d);
        a6 += __shfl_xor_sync(0xffffffffu, a6, d);
        a7 += __shfl_xor_sync(0xffffffffu, a7, d);
    }
    if (sg4 == 0) {
        uint4 o = { packh2(a0, a1), packh2(a2, a3), packh2(a4, a5), packh2(a6, a7) };
        *reinterpret_cast<uint4*>(tmp + (size_t)bq * 256 + h * HEAD_DIM + 8 * c4) = o;
    }
}

// ---------------------------------------------------------------------------
extern "C" void kernel_launch(void* const* d_in, const int* in_sizes, int n_in,
                              void* d_out, int out_size)
{
    const float* query  = (const float*)d_in[0];
    const float* refpts = (const float*)d_in[1];
    const float* value  = (const float*)d_in[2];
    const int*   shapes = (const int*)  d_in[3];
    const int*   starts = (const int*)  d_in[4];
    const float* W_off  = (const float*)d_in[5];
    const float* b_off  = (const float*)d_in[6];
    const float* W_attn = (const float*)d_in[7];
    const float* b_attn = (const float*)d_in[8];
    const float* W_val  = (const float*)d_in[9];
    const float* b_val  = (const float*)d_in[10];
    const float* W_out  = (const float*)d_in[11];
    const float* b_out  = (const float*)d_in[12];
    float* out = (float*)d_out;

    __half *pvh, *pwt, *ptmph;
    float *pqp;
    cudaGetSymbolAddress((void**)&pvh,   g_vh);
    cudaGetSymbolAddress((void**)&pqp,   g_qp);
    cudaGetSymbolAddress((void**)&ptmph, g_tmph);
    cudaGetSymbolAddress((void**)&pwt,   g_wt);

    const int SMEMF = (2 * 128 * 20 + 3 * 128 * 20) * 4;   // 51200 B
    const int SMEMO = (32 + 128) * 528;                    // 84480 B
    cudaFuncSetAttribute(gemm_fused, cudaFuncAttributeMaxDynamicSharedMemorySize, SMEMF);
    cudaFuncSetAttribute(gemm_out,   cudaFuncAttributeMaxDynamicSharedMemorySize, SMEMO);

    // 0) transpose+convert all weights to fp16 [n][k]
    transpose_w<<<dim3(8, 8, 4), dim3(32, 8)>>>(W_val, W_off, W_attn, W_out, pwt);
    // 1) value projection (fp16 out) + combined query projection, one launch
    gemm_fused<<<NVB + NQB, 256, SMEMF>>>(value, query, pwt,
                                          b_val, b_off, b_attn, pvh, pqp);
    // 2) fused softmax + sampling -> fp16 tmp
    msda_sample<<<BQ, 256>>>(refpts, pqp, shapes, starts, pvh, ptmph);
    // 3) output projection: single-stage BM=32, [7200,256] @ [256,256]
    {
        dim3 grid(2, (BQ + 31) / 32);
        gemm_out<<<grid, 256, SMEMO>>>(ptmph, pwt, b_out, out);
    }
}